// round 2
// baseline (speedup 1.0000x reference)
#include <cuda_runtime.h>
#include <math.h>
#include <stdint.h>

#define VOCAB 50257
#define EDIM  256
#define HDIM  512
#define G3    1536
#define BATCH 64
#define LSEQ  64
#define SOS_TOK 2

// ---------------- persistent device state (no allocations allowed) ----------
__device__ float g_h[BATCH * HDIM];                    // current hidden state
__device__ float g_gi_part[4 * BATCH * G3];            // split-K partials (x @ W_ih^T)
__device__ float g_gh_part[4 * BATCH * G3];            // split-K partials (h @ W_hh^T)
__device__ unsigned long long g_amax[BATCH * 32];      // padded argmax slots (256B apart)

// ---------------------------------------------------------------------------
// Kernel 1: GRU input/hidden GEMMs, deterministic split-K (4 splits).
// grid = (48 j-tiles of 32, 4 splits), block = 128 threads.
// Thread computes 4j x 4b for both gi (K=256, split 64) and gh (K=512, split 128).
// ---------------------------------------------------------------------------
__global__ __launch_bounds__(128) void gru_gemm_kernel(
    int s,
    const float* __restrict__ h0,
    const float* __restrict__ emb,
    const float* __restrict__ W_ih,
    const float* __restrict__ W_hh)
{
    __shared__ int   stok[BATCH];
    __shared__ float as_[64][65];   // [k][b]  (+1 pad: conflict-free)
    __shared__ float ws_[64][33];   // [k][j]  (+1 pad)

    const int tid   = threadIdx.x;
    const int jt    = blockIdx.x;     // 0..47
    const int split = blockIdx.y;     // 0..3
    const int j0    = jt * 32;
    const int tj    = tid & 7;        // j lane
    const int tb    = tid >> 3;       // b lane (0..15)

    if (tid < BATCH) {
        int t;
        if (s == 0) t = SOS_TOK;
        else        t = (int)(~(unsigned int)(g_amax[tid * 32] & 0xFFFFFFFFull));
        stok[tid] = t;
    }
    __syncthreads();

    const float* __restrict__ hprev = (s == 0) ? h0 : g_h;

    float acci[16], acch[16];
    #pragma unroll
    for (int i = 0; i < 16; i++) { acci[i] = 0.f; acch[i] = 0.f; }

    // ---------------- chunk 0: gi over x = emb[tok], K-range [split*64, +64)
    {
        const int k0 = split * 64;
        #pragma unroll
        for (int i = 0; i < 32; i++) {
            int idx = tid + 128 * i;
            int k = idx & 63, b = idx >> 6;
            as_[k][b] = emb[(size_t)stok[b] * EDIM + k0 + k];
        }
        #pragma unroll
        for (int i = 0; i < 16; i++) {
            int idx = tid + 128 * i;
            int k = idx & 63, j = idx >> 6;
            ws_[k][j] = W_ih[(size_t)(j0 + j) * EDIM + k0 + k];
        }
        __syncthreads();
        #pragma unroll 4
        for (int k = 0; k < 64; k++) {
            float a0 = as_[k][tb], a1 = as_[k][tb + 16], a2 = as_[k][tb + 32], a3 = as_[k][tb + 48];
            #pragma unroll
            for (int ji = 0; ji < 4; ji++) {
                float w = ws_[k][tj + 8 * ji];
                acci[ji * 4 + 0] += w * a0;
                acci[ji * 4 + 1] += w * a1;
                acci[ji * 4 + 2] += w * a2;
                acci[ji * 4 + 3] += w * a3;
            }
        }
        __syncthreads();
    }

    // ---------------- chunks 1,2: gh over hprev, K-range [split*128, +128)
    for (int c = 0; c < 2; c++) {
        const int k0 = split * 128 + c * 64;
        #pragma unroll
        for (int i = 0; i < 32; i++) {
            int idx = tid + 128 * i;
            int k = idx & 63, b = idx >> 6;
            as_[k][b] = hprev[b * HDIM + k0 + k];
        }
        #pragma unroll
        for (int i = 0; i < 16; i++) {
            int idx = tid + 128 * i;
            int k = idx & 63, j = idx >> 6;
            ws_[k][j] = W_hh[(size_t)(j0 + j) * HDIM + k0 + k];
        }
        __syncthreads();
        #pragma unroll 4
        for (int k = 0; k < 64; k++) {
            float a0 = as_[k][tb], a1 = as_[k][tb + 16], a2 = as_[k][tb + 32], a3 = as_[k][tb + 48];
            #pragma unroll
            for (int ji = 0; ji < 4; ji++) {
                float w = ws_[k][tj + 8 * ji];
                acch[ji * 4 + 0] += w * a0;
                acch[ji * 4 + 1] += w * a1;
                acch[ji * 4 + 2] += w * a2;
                acch[ji * 4 + 3] += w * a3;
            }
        }
        __syncthreads();
    }

    // ---------------- store partials
    const int sb = split * BATCH;
    #pragma unroll
    for (int ji = 0; ji < 4; ji++) {
        int j = j0 + tj + 8 * ji;
        #pragma unroll
        for (int bi = 0; bi < 4; bi++) {
            int b = tb + 16 * bi;
            g_gi_part[(size_t)(sb + b) * G3 + j] = acci[ji * 4 + bi];
            g_gh_part[(size_t)(sb + b) * G3 + j] = acch[ji * 4 + bi];
        }
    }
}

// ---------------------------------------------------------------------------
// Kernel 2: combine split-K partials (fixed order -> deterministic), gate math,
// h_new update (in place), and reset of argmax slots for this step.
// grid = 64 (b), block = 512 (j).
// ---------------------------------------------------------------------------
__global__ __launch_bounds__(512) void gru_combine_kernel(
    int s,
    const float* __restrict__ h0,
    const float* __restrict__ b_ih,
    const float* __restrict__ b_hh)
{
    const int b = blockIdx.x;
    const int j = threadIdx.x;

    float gir = 0.f, giz = 0.f, gin = 0.f, ghr = 0.f, ghz = 0.f, ghn = 0.f;
    #pragma unroll
    for (int sp = 0; sp < 4; sp++) {
        const float* gi = g_gi_part + (size_t)(sp * BATCH + b) * G3;
        const float* gh = g_gh_part + (size_t)(sp * BATCH + b) * G3;
        gir += gi[j];            giz += gi[j + HDIM];     gin += gi[j + 2 * HDIM];
        ghr += gh[j];            ghz += gh[j + HDIM];     ghn += gh[j + 2 * HDIM];
    }
    gir += b_ih[j];  giz += b_ih[j + HDIM];  gin += b_ih[j + 2 * HDIM];
    ghr += b_hh[j];  ghz += b_hh[j + HDIM];  ghn += b_hh[j + 2 * HDIM];

    float r = 1.f / (1.f + expf(-(gir + ghr)));
    float z = 1.f / (1.f + expf(-(giz + ghz)));
    float n = tanhf(gin + r * ghn);

    float hold = (s == 0) ? h0[b * HDIM + j] : g_h[b * HDIM + j];
    g_h[b * HDIM + j] = (1.f - z) * n + z * hold;

    // reset argmax slots before this step's classifier runs
    if (b == 0 && j < BATCH) g_amax[j * 32] = 0ull;
}

// ---------------------------------------------------------------------------
// Kernel 3: classifier logits = h @ Wc^T + bc, write out, fused argmax.
// grid = 393 v-tiles of 128, block = 128 threads.
// Thread (tv=tid&15, tb=tid>>4) computes 8v x 8b with v = vg + tv + 16*vi
// (lane-consecutive v -> coalesced stores, conflict-free smem reads).
// ---------------------------------------------------------------------------
__device__ __forceinline__ unsigned int order_enc(float f) {
    unsigned int u = __float_as_uint(f);
    return (u & 0x80000000u) ? ~u : (u | 0x80000000u);
}

__global__ __launch_bounds__(128, 2) void cls_kernel(
    int s,
    const float* __restrict__ Wc,
    const float* __restrict__ bc,
    float* __restrict__ out)
{
    __shared__ float ws_[16][128];  // [k][v]
    __shared__ float hs_[16][64];   // [k][b]

    const int tid = threadIdx.x;
    const int tv  = tid & 15;
    const int tb  = tid >> 4;       // 0..7
    const int vg  = blockIdx.x * 128;

    float acc[8][8];                // [vi][bi]
    #pragma unroll
    for (int vi = 0; vi < 8; vi++)
        #pragma unroll
        for (int bi = 0; bi < 8; bi++) acc[vi][bi] = 0.f;

    for (int kc = 0; kc < HDIM / 16; kc++) {
        const int k0 = kc * 16;
        // Wc tile (transposed into smem); rows loaded in 64B segments
        #pragma unroll
        for (int i = 0; i < 4; i++) {
            int idx = tid + 128 * i;
            int v = idx >> 2, kq = idx & 3;
            int vglob = vg + v;
            float4 w = (vglob < VOCAB)
                ? *(const float4*)(Wc + (size_t)vglob * HDIM + k0 + 4 * kq)
                : make_float4(0.f, 0.f, 0.f, 0.f);
            ws_[4 * kq + 0][v] = w.x;
            ws_[4 * kq + 1][v] = w.y;
            ws_[4 * kq + 2][v] = w.z;
            ws_[4 * kq + 3][v] = w.w;
        }
        // h tile
        #pragma unroll
        for (int i = 0; i < 8; i++) {
            int idx = tid + 128 * i;
            int k = idx & 15, b = idx >> 4;
            hs_[k][b] = g_h[b * HDIM + k0 + k];
        }
        __syncthreads();

        #pragma unroll
        for (int k = 0; k < 16; k++) {
            float hreg[8], wreg[8];
            #pragma unroll
            for (int bi = 0; bi < 8; bi++) hreg[bi] = hs_[k][8 * tb + bi];
            #pragma unroll
            for (int vi = 0; vi < 8; vi++) wreg[vi] = ws_[k][tv + 16 * vi];
            #pragma unroll
            for (int vi = 0; vi < 8; vi++)
                #pragma unroll
                for (int bi = 0; bi < 8; bi++)
                    acc[vi][bi] += wreg[vi] * hreg[bi];
        }
        __syncthreads();
    }

    // epilogue: bias, store, argmax
    unsigned long long key[8];
    #pragma unroll
    for (int bi = 0; bi < 8; bi++) key[bi] = 0ull;

    #pragma unroll
    for (int vi = 0; vi < 8; vi++) {
        int v = vg + tv + 16 * vi;
        if (v < VOCAB) {
            float bcv = bc[v];
            #pragma unroll
            for (int bi = 0; bi < 8; bi++) {
                float logit = acc[vi][bi] + bcv;
                int b = 8 * tb + bi;
                out[(size_t)(s * BATCH + b) * VOCAB + v] = logit;
                unsigned long long k2 =
                    ((unsigned long long)order_enc(logit) << 32) |
                    (unsigned long long)(unsigned int)(~v);
                if (k2 > key[bi]) key[bi] = k2;
            }
        }
    }

    // reduce across the 16 tv lanes (shfl stays inside each 16-lane half)
    #pragma unroll
    for (int bi = 0; bi < 8; bi++) {
        unsigned long long k2 = key[bi];
        #pragma unroll
        for (int d = 8; d > 0; d >>= 1) {
            unsigned long long o = __shfl_xor_sync(0xFFFFFFFFu, k2, d);
            if (o > k2) k2 = o;
        }
        key[bi] = k2;
    }
    if (tv == 0) {
        #pragma unroll
        for (int bi = 0; bi < 8; bi++)
            atomicMax(&g_amax[(8 * tb + bi) * 32], key[bi]);
    }
}

// ---------------------------------------------------------------------------
// Launch: 64 steps x (gru_gemm -> gru_combine -> classifier), all on the
// default stream so the whole sequence is captured into one graph.
// ---------------------------------------------------------------------------
extern "C" void kernel_launch(void* const* d_in, const int* in_sizes, int n_in,
                              void* d_out, int out_size)
{
    const float* h0   = (const float*)d_in[0];
    const float* emb  = (const float*)d_in[1];
    const float* W_ih = (const float*)d_in[2];
    const float* W_hh = (const float*)d_in[3];
    const float* b_ih = (const float*)d_in[4];
    const float* b_hh = (const float*)d_in[5];
    const float* Wc   = (const float*)d_in[6];
    const float* bc   = (const float*)d_in[7];
    float* out = (float*)d_out;

    const int n_vtiles = (VOCAB + 127) / 128;  // 393

    for (int s = 0; s < LSEQ; s++) {
        gru_gemm_kernel<<<dim3(48, 4), 128>>>(s, h0, emb, W_ih, W_hh);
        gru_combine_kernel<<<BATCH, 512>>>(s, h0, b_ih, b_hh);
        cls_kernel<<<n_vtiles, 128>>>(s, Wc, bc, out);
    }
}